// round 1
// baseline (speedup 1.0000x reference)
#include <cuda_runtime.h>

#define N_NODES 2000
#define BATCH 512
#define N_TOTAL (BATCH * N_NODES)      // 1,024,000
#define N_EDGES (16 * N_TOTAL)         // 16,384,000
#define SLOPE 0.01f

// Scratch (device globals: allowed, no allocation)
__device__ float g_agg[(size_t)N_TOTAL * 16];  // 64 MB, reused as 8-wide after layer 0
__device__ float g_h[(size_t)N_TOTAL * 8];     // 32 MB
__device__ float g_z[N_TOTAL];                 // 4 MB

__device__ __forceinline__ float leaky(float v) {
    return v > 0.0f ? v : SLOPE * v;
}

// ---------------- zero the 16-wide agg buffer ----------------
__global__ void zero_agg16() {
    unsigned i = blockIdx.x * blockDim.x + threadIdx.x;   // float4 index
    const unsigned n4 = (unsigned)N_TOTAL * 4;            // 4,096,000 float4s
    if (i < n4) reinterpret_cast<float4*>(g_agg)[i] = make_float4(0.f, 0.f, 0.f, 0.f);
}

// ---------------- scatter: F=16 (layer 0, reads x) ----------------
__global__ void scatter16(const int* __restrict__ ei, const float* __restrict__ x) {
    unsigned g = blockIdx.x * blockDim.x + threadIdx.x;
    unsigned e = g >> 4;
    unsigned f = g & 15u;
    if (e < (unsigned)N_EDGES) {
        int src = __ldg(ei + e);
        int dst = __ldg(ei + N_EDGES + e);
        float v = __ldg(x + (size_t)src * 16 + f);
        atomicAdd(&g_agg[(size_t)dst * 16 + f], v);
    }
}

// ---------------- scatter: F=8 (layers 1-3, reads g_h) ----------------
__global__ void scatter8(const int* __restrict__ ei) {
    unsigned g = blockIdx.x * blockDim.x + threadIdx.x;
    unsigned e = g >> 3;
    unsigned f = g & 7u;
    if (e < (unsigned)N_EDGES) {
        int src = __ldg(ei + e);
        int dst = __ldg(ei + N_EDGES + e);
        float v = g_h[(size_t)src * 8 + f];
        atomicAdd(&g_agg[(size_t)dst * 8 + f], v);
    }
}

// ---------------- MLP layer 0: agg16 + x -> Lin(16,8) lrelu Lin(8,8) lrelu ----------------
__global__ void mlp0_kernel(const float* __restrict__ x,
                            const float* __restrict__ wa, const float* __restrict__ ba,
                            const float* __restrict__ wb, const float* __restrict__ bb) {
    __shared__ float swa[128], swb[64], sba[8], sbb[8];
    int t = threadIdx.x;
    if (t < 128) swa[t] = wa[t];
    if (t < 64)  swb[t] = wb[t];
    if (t < 8)   { sba[t] = ba[t]; sbb[t] = bb[t]; }
    __syncthreads();

    unsigned i = blockIdx.x * blockDim.x + t;
    if (i >= (unsigned)N_TOTAL) return;

    float in[16];
    const float4* ax = reinterpret_cast<const float4*>(x + (size_t)i * 16);
    const float4* ag = reinterpret_cast<const float4*>(g_agg + (size_t)i * 16);
#pragma unroll
    for (int q = 0; q < 4; q++) {
        float4 a = ag[q];
        float4 b = ax[q];
        in[4 * q + 0] = a.x + b.x;
        in[4 * q + 1] = a.y + b.y;
        in[4 * q + 2] = a.z + b.z;
        in[4 * q + 3] = a.w + b.w;
    }

    float m[8];
#pragma unroll
    for (int j = 0; j < 8; j++) m[j] = sba[j];
#pragma unroll
    for (int k = 0; k < 16; k++) {
        float v = in[k];
#pragma unroll
        for (int j = 0; j < 8; j++) m[j] = fmaf(v, swa[k * 8 + j], m[j]);
    }
#pragma unroll
    for (int j = 0; j < 8; j++) m[j] = leaky(m[j]);

    float o[8];
#pragma unroll
    for (int j = 0; j < 8; j++) o[j] = sbb[j];
#pragma unroll
    for (int k = 0; k < 8; k++) {
        float v = m[k];
#pragma unroll
        for (int j = 0; j < 8; j++) o[j] = fmaf(v, swb[k * 8 + j], o[j]);
    }
#pragma unroll
    for (int j = 0; j < 8; j++) o[j] = leaky(o[j]);  // inter-layer activation

    float4 lo = make_float4(o[0], o[1], o[2], o[3]);
    float4 hi = make_float4(o[4], o[5], o[6], o[7]);
    float4* ph = reinterpret_cast<float4*>(g_h + (size_t)i * 8);
    float4* pa = reinterpret_cast<float4*>(g_agg + (size_t)i * 8);  // seed next layer's self term
    ph[0] = lo; ph[1] = hi;
    pa[0] = lo; pa[1] = hi;
}

// ---------------- MLP layers 1-2: agg8 -> Lin(8,8) lrelu Lin(8,8) lrelu ----------------
__global__ void mlp_mid_kernel(const float* __restrict__ wa, const float* __restrict__ ba,
                               const float* __restrict__ wb, const float* __restrict__ bb) {
    __shared__ float swa[64], swb[64], sba[8], sbb[8];
    int t = threadIdx.x;
    if (t < 64) { swa[t] = wa[t]; swb[t] = wb[t]; }
    if (t < 8)  { sba[t] = ba[t]; sbb[t] = bb[t]; }
    __syncthreads();

    unsigned i = blockIdx.x * blockDim.x + t;
    if (i >= (unsigned)N_TOTAL) return;

    const float4* ag = reinterpret_cast<const float4*>(g_agg + (size_t)i * 8);
    float4 a0 = ag[0], a1 = ag[1];
    float in[8] = {a0.x, a0.y, a0.z, a0.w, a1.x, a1.y, a1.z, a1.w};

    float m[8];
#pragma unroll
    for (int j = 0; j < 8; j++) m[j] = sba[j];
#pragma unroll
    for (int k = 0; k < 8; k++) {
        float v = in[k];
#pragma unroll
        for (int j = 0; j < 8; j++) m[j] = fmaf(v, swa[k * 8 + j], m[j]);
    }
#pragma unroll
    for (int j = 0; j < 8; j++) m[j] = leaky(m[j]);

    float o[8];
#pragma unroll
    for (int j = 0; j < 8; j++) o[j] = sbb[j];
#pragma unroll
    for (int k = 0; k < 8; k++) {
        float v = m[k];
#pragma unroll
        for (int j = 0; j < 8; j++) o[j] = fmaf(v, swb[k * 8 + j], o[j]);
    }
#pragma unroll
    for (int j = 0; j < 8; j++) o[j] = leaky(o[j]);

    float4 lo = make_float4(o[0], o[1], o[2], o[3]);
    float4 hi = make_float4(o[4], o[5], o[6], o[7]);
    float4* ph = reinterpret_cast<float4*>(g_h + (size_t)i * 8);
    float4* pa = reinterpret_cast<float4*>(g_agg + (size_t)i * 8);
    ph[0] = lo; ph[1] = hi;
    pa[0] = lo; pa[1] = hi;
}

// ---------------- MLP layer 3 + fc1 fused: agg8 -> conv3 (no act) -> leaky -> fc1 -> g_z ----------------
__global__ void mlp_last_kernel(const float* __restrict__ wa, const float* __restrict__ ba,
                                const float* __restrict__ wb, const float* __restrict__ bb,
                                const float* __restrict__ fc1w, const float* __restrict__ fc1b) {
    __shared__ float swa[64], swb[64], sba[8], sbb[8], sf1[8], sf1b;
    int t = threadIdx.x;
    if (t < 64) { swa[t] = wa[t]; swb[t] = wb[t]; }
    if (t < 8)  { sba[t] = ba[t]; sbb[t] = bb[t]; sf1[t] = fc1w[t]; }
    if (t == 0) sf1b = fc1b[0];
    __syncthreads();

    unsigned i = blockIdx.x * blockDim.x + t;
    if (i >= (unsigned)N_TOTAL) return;

    const float4* ag = reinterpret_cast<const float4*>(g_agg + (size_t)i * 8);
    float4 a0 = ag[0], a1 = ag[1];
    float in[8] = {a0.x, a0.y, a0.z, a0.w, a1.x, a1.y, a1.z, a1.w};

    float m[8];
#pragma unroll
    for (int j = 0; j < 8; j++) m[j] = sba[j];
#pragma unroll
    for (int k = 0; k < 8; k++) {
        float v = in[k];
#pragma unroll
        for (int j = 0; j < 8; j++) m[j] = fmaf(v, swa[k * 8 + j], m[j]);
    }
#pragma unroll
    for (int j = 0; j < 8; j++) m[j] = leaky(m[j]);

    float o[8];
#pragma unroll
    for (int j = 0; j < 8; j++) o[j] = sbb[j];
#pragma unroll
    for (int k = 0; k < 8; k++) {
        float v = m[k];
#pragma unroll
        for (int j = 0; j < 8; j++) o[j] = fmaf(v, swb[k * 8 + j], o[j]);
    }
    // no inter-layer act after last conv; readout applies leaky before fc1
    float z = sf1b;
#pragma unroll
    for (int j = 0; j < 8; j++) z = fmaf(leaky(o[j]), sf1[j], z);
    g_z[i] = z;
}

// ---------------- readout: per-graph fc2 + log_softmax ----------------
__global__ void readout_kernel(const float* __restrict__ fc2w, const float* __restrict__ fc2b,
                               float* __restrict__ out) {
    int b = blockIdx.x;
    int t = threadIdx.x;
    float s0 = 0.f, s1 = 0.f;
    const float* zb = g_z + (size_t)b * N_NODES;
    for (int n = t; n < N_NODES; n += blockDim.x) {
        float zv = leaky(zb[n]);
        float2 w = __ldg(reinterpret_cast<const float2*>(fc2w) + n);
        s0 = fmaf(zv, w.x, s0);
        s1 = fmaf(zv, w.y, s1);
    }
    // warp reduce
#pragma unroll
    for (int o = 16; o > 0; o >>= 1) {
        s0 += __shfl_down_sync(0xFFFFFFFFu, s0, o);
        s1 += __shfl_down_sync(0xFFFFFFFFu, s1, o);
    }
    __shared__ float r0[8], r1[8];
    int w = t >> 5, lane = t & 31;
    if (lane == 0) { r0[w] = s0; r1[w] = s1; }
    __syncthreads();
    if (t == 0) {
        float a0 = 0.f, a1 = 0.f;
#pragma unroll
        for (int k = 0; k < 8; k++) { a0 += r0[k]; a1 += r1[k]; }
        a0 += fc2b[0];
        a1 += fc2b[1];
        float mx = fmaxf(a0, a1);
        float lse = mx + logf(expf(a0 - mx) + expf(a1 - mx));
        out[2 * b + 0] = a0 - lse;
        out[2 * b + 1] = a1 - lse;
    }
}

extern "C" void kernel_launch(void* const* d_in, const int* in_sizes, int n_in,
                              void* d_out, int out_size) {
    const float* x  = (const float*)d_in[0];
    const int*   ei = (const int*)d_in[1];

    // batch_size may or may not be materialized as a size-1 input at index 2.
    // w0a has 128 elements -> detect.
    int base = (in_sizes[2] == 128) ? 2 : 3;

    const float* W[16];
    for (int k = 0; k < 16; k++) W[k] = (const float*)d_in[base + k];
    const float* fc1w = (const float*)d_in[base + 16];
    const float* fc1b = (const float*)d_in[base + 17];
    const float* fc2w = (const float*)d_in[base + 18];
    const float* fc2b = (const float*)d_in[base + 19];
    float* out = (float*)d_out;

    const int TB = 256;
    unsigned nodeBlocks = (N_TOTAL + TB - 1) / TB;
    unsigned s16Blocks  = ((unsigned)N_EDGES * 16 + TB - 1) / TB;
    unsigned s8Blocks   = ((unsigned)N_EDGES * 8 + TB - 1) / TB;
    unsigned zBlocks    = ((unsigned)N_TOTAL * 4 + TB - 1) / TB;

    // Layer 0
    zero_agg16<<<zBlocks, TB>>>();
    scatter16<<<s16Blocks, TB>>>(ei, x);
    mlp0_kernel<<<nodeBlocks, TB>>>(x, W[0], W[1], W[2], W[3]);

    // Layer 1
    scatter8<<<s8Blocks, TB>>>(ei);
    mlp_mid_kernel<<<nodeBlocks, TB>>>(W[4], W[5], W[6], W[7]);

    // Layer 2
    scatter8<<<s8Blocks, TB>>>(ei);
    mlp_mid_kernel<<<nodeBlocks, TB>>>(W[8], W[9], W[10], W[11]);

    // Layer 3 (+ fc1 fused)
    scatter8<<<s8Blocks, TB>>>(ei);
    mlp_last_kernel<<<nodeBlocks, TB>>>(W[12], W[13], W[14], W[15], fc1w, fc1b);

    // Readout
    readout_kernel<<<BATCH, TB>>>(fc2w, fc2b, out);
}

// round 2
// speedup vs baseline: 2.3512x; 2.3512x over previous
#include <cuda_runtime.h>

#define N_NODES 2000
#define BATCH 512
#define N_TOTAL (BATCH * N_NODES)      // 1,024,000
#define N_EDGES (16 * N_TOTAL)         // 16,384,000
#define SLOPE 0.01f

// Scratch (device globals: allowed, no allocation). 16B-aligned for float4 / red.v4.
__device__ __align__(16) float g_agg[(size_t)N_TOTAL * 16];  // 64 MB, reused as 8-wide after layer 0
__device__ __align__(16) float g_h[(size_t)N_TOTAL * 8];     // 32 MB
__device__ __align__(16) float g_z[N_TOTAL];                 // 4 MB

__device__ __forceinline__ float leaky(float v) {
    return v > 0.0f ? v : SLOPE * v;
}

__device__ __forceinline__ void red_add_v4(float* addr, float4 v) {
    asm volatile("red.global.add.v4.f32 [%0], {%1, %2, %3, %4};"
                 :: "l"(addr), "f"(v.x), "f"(v.y), "f"(v.z), "f"(v.w)
                 : "memory");
}

// ---------------- zero the 16-wide agg buffer ----------------
__global__ void zero_agg16() {
    unsigned i = blockIdx.x * blockDim.x + threadIdx.x;   // float4 index
    const unsigned n4 = (unsigned)N_TOTAL * 4;            // 4,096,000 float4s
    if (i < n4) reinterpret_cast<float4*>(g_agg)[i] = make_float4(0.f, 0.f, 0.f, 0.f);
}

// ---------------- scatter: F=16 (layer 0, reads x), 4 lanes/edge, red.v4 ----------------
__global__ void scatter16(const int* __restrict__ ei, const float* __restrict__ x) {
    unsigned g = blockIdx.x * blockDim.x + threadIdx.x;
    unsigned e = g >> 2;          // 4 lanes per edge
    unsigned f = g & 3u;          // float4 chunk 0..3
    if (e < (unsigned)N_EDGES) {
        int src = __ldg(ei + e);
        int dst = __ldg(ei + N_EDGES + e);
        float4 v = __ldg(reinterpret_cast<const float4*>(x + (size_t)src * 16) + f);
        red_add_v4(g_agg + (size_t)dst * 16 + f * 4, v);
    }
}

// ---------------- scatter: F=8 (layers 1-3, reads g_h), 2 lanes/edge, red.v4 ----------------
__global__ void scatter8(const int* __restrict__ ei) {
    unsigned g = blockIdx.x * blockDim.x + threadIdx.x;
    unsigned e = g >> 1;          // 2 lanes per edge
    unsigned f = g & 1u;          // float4 chunk 0..1
    if (e < (unsigned)N_EDGES) {
        int src = __ldg(ei + e);
        int dst = __ldg(ei + N_EDGES + e);
        float4 v = *reinterpret_cast<const float4*>(g_h + (size_t)src * 8 + f * 4);
        red_add_v4(g_agg + (size_t)dst * 8 + f * 4, v);
    }
}

// ---------------- MLP layer 0: agg16 + x -> Lin(16,8) lrelu Lin(8,8) lrelu ----------------
__global__ void mlp0_kernel(const float* __restrict__ x,
                            const float* __restrict__ wa, const float* __restrict__ ba,
                            const float* __restrict__ wb, const float* __restrict__ bb) {
    __shared__ float swa[128], swb[64], sba[8], sbb[8];
    int t = threadIdx.x;
    if (t < 128) swa[t] = wa[t];
    if (t < 64)  swb[t] = wb[t];
    if (t < 8)   { sba[t] = ba[t]; sbb[t] = bb[t]; }
    __syncthreads();

    unsigned i = blockIdx.x * blockDim.x + t;
    if (i >= (unsigned)N_TOTAL) return;

    float in[16];
    const float4* ax = reinterpret_cast<const float4*>(x + (size_t)i * 16);
    const float4* ag = reinterpret_cast<const float4*>(g_agg + (size_t)i * 16);
#pragma unroll
    for (int q = 0; q < 4; q++) {
        float4 a = ag[q];
        float4 b = ax[q];
        in[4 * q + 0] = a.x + b.x;
        in[4 * q + 1] = a.y + b.y;
        in[4 * q + 2] = a.z + b.z;
        in[4 * q + 3] = a.w + b.w;
    }

    float m[8];
#pragma unroll
    for (int j = 0; j < 8; j++) m[j] = sba[j];
#pragma unroll
    for (int k = 0; k < 16; k++) {
        float v = in[k];
#pragma unroll
        for (int j = 0; j < 8; j++) m[j] = fmaf(v, swa[k * 8 + j], m[j]);
    }
#pragma unroll
    for (int j = 0; j < 8; j++) m[j] = leaky(m[j]);

    float o[8];
#pragma unroll
    for (int j = 0; j < 8; j++) o[j] = sbb[j];
#pragma unroll
    for (int k = 0; k < 8; k++) {
        float v = m[k];
#pragma unroll
        for (int j = 0; j < 8; j++) o[j] = fmaf(v, swb[k * 8 + j], o[j]);
    }
#pragma unroll
    for (int j = 0; j < 8; j++) o[j] = leaky(o[j]);  // inter-layer activation

    float4 lo = make_float4(o[0], o[1], o[2], o[3]);
    float4 hi = make_float4(o[4], o[5], o[6], o[7]);
    float4* ph = reinterpret_cast<float4*>(g_h + (size_t)i * 8);
    float4* pa = reinterpret_cast<float4*>(g_agg + (size_t)i * 8);  // seed next layer's self term
    ph[0] = lo; ph[1] = hi;
    pa[0] = lo; pa[1] = hi;
}

// ---------------- MLP layers 1-2: agg8 -> Lin(8,8) lrelu Lin(8,8) lrelu ----------------
__global__ void mlp_mid_kernel(const float* __restrict__ wa, const float* __restrict__ ba,
                               const float* __restrict__ wb, const float* __restrict__ bb) {
    __shared__ float swa[64], swb[64], sba[8], sbb[8];
    int t = threadIdx.x;
    if (t < 64) { swa[t] = wa[t]; swb[t] = wb[t]; }
    if (t < 8)  { sba[t] = ba[t]; sbb[t] = bb[t]; }
    __syncthreads();

    unsigned i = blockIdx.x * blockDim.x + t;
    if (i >= (unsigned)N_TOTAL) return;

    const float4* ag = reinterpret_cast<const float4*>(g_agg + (size_t)i * 8);
    float4 a0 = ag[0], a1 = ag[1];
    float in[8] = {a0.x, a0.y, a0.z, a0.w, a1.x, a1.y, a1.z, a1.w};

    float m[8];
#pragma unroll
    for (int j = 0; j < 8; j++) m[j] = sba[j];
#pragma unroll
    for (int k = 0; k < 8; k++) {
        float v = in[k];
#pragma unroll
        for (int j = 0; j < 8; j++) m[j] = fmaf(v, swa[k * 8 + j], m[j]);
    }
#pragma unroll
    for (int j = 0; j < 8; j++) m[j] = leaky(m[j]);

    float o[8];
#pragma unroll
    for (int j = 0; j < 8; j++) o[j] = sbb[j];
#pragma unroll
    for (int k = 0; k < 8; k++) {
        float v = m[k];
#pragma unroll
        for (int j = 0; j < 8; j++) o[j] = fmaf(v, swb[k * 8 + j], o[j]);
    }
#pragma unroll
    for (int j = 0; j < 8; j++) o[j] = leaky(o[j]);

    float4 lo = make_float4(o[0], o[1], o[2], o[3]);
    float4 hi = make_float4(o[4], o[5], o[6], o[7]);
    float4* ph = reinterpret_cast<float4*>(g_h + (size_t)i * 8);
    float4* pa = reinterpret_cast<float4*>(g_agg + (size_t)i * 8);
    ph[0] = lo; ph[1] = hi;
    pa[0] = lo; pa[1] = hi;
}

// ---------------- MLP layer 3 + fc1 fused: agg8 -> conv3 (no act) -> leaky -> fc1 -> g_z ----------------
__global__ void mlp_last_kernel(const float* __restrict__ wa, const float* __restrict__ ba,
                                const float* __restrict__ wb, const float* __restrict__ bb,
                                const float* __restrict__ fc1w, const float* __restrict__ fc1b) {
    __shared__ float swa[64], swb[64], sba[8], sbb[8], sf1[8], sf1b;
    int t = threadIdx.x;
    if (t < 64) { swa[t] = wa[t]; swb[t] = wb[t]; }
    if (t < 8)  { sba[t] = ba[t]; sbb[t] = bb[t]; sf1[t] = fc1w[t]; }
    if (t == 0) sf1b = fc1b[0];
    __syncthreads();

    unsigned i = blockIdx.x * blockDim.x + t;
    if (i >= (unsigned)N_TOTAL) return;

    const float4* ag = reinterpret_cast<const float4*>(g_agg + (size_t)i * 8);
    float4 a0 = ag[0], a1 = ag[1];
    float in[8] = {a0.x, a0.y, a0.z, a0.w, a1.x, a1.y, a1.z, a1.w};

    float m[8];
#pragma unroll
    for (int j = 0; j < 8; j++) m[j] = sba[j];
#pragma unroll
    for (int k = 0; k < 8; k++) {
        float v = in[k];
#pragma unroll
        for (int j = 0; j < 8; j++) m[j] = fmaf(v, swa[k * 8 + j], m[j]);
    }
#pragma unroll
    for (int j = 0; j < 8; j++) m[j] = leaky(m[j]);

    float o[8];
#pragma unroll
    for (int j = 0; j < 8; j++) o[j] = sbb[j];
#pragma unroll
    for (int k = 0; k < 8; k++) {
        float v = m[k];
#pragma unroll
        for (int j = 0; j < 8; j++) o[j] = fmaf(v, swb[k * 8 + j], o[j]);
    }
    // no inter-layer act after last conv; readout applies leaky before fc1
    float z = sf1b;
#pragma unroll
    for (int j = 0; j < 8; j++) z = fmaf(leaky(o[j]), sf1[j], z);
    g_z[i] = z;
}

// ---------------- readout: per-graph fc2 + log_softmax ----------------
__global__ void readout_kernel(const float* __restrict__ fc2w, const float* __restrict__ fc2b,
                               float* __restrict__ out) {
    int b = blockIdx.x;
    int t = threadIdx.x;
    float s0 = 0.f, s1 = 0.f;
    const float* zb = g_z + (size_t)b * N_NODES;
    for (int n = t; n < N_NODES; n += blockDim.x) {
        float zv = leaky(zb[n]);
        float2 w = __ldg(reinterpret_cast<const float2*>(fc2w) + n);
        s0 = fmaf(zv, w.x, s0);
        s1 = fmaf(zv, w.y, s1);
    }
    // warp reduce
#pragma unroll
    for (int o = 16; o > 0; o >>= 1) {
        s0 += __shfl_down_sync(0xFFFFFFFFu, s0, o);
        s1 += __shfl_down_sync(0xFFFFFFFFu, s1, o);
    }
    __shared__ float r0[8], r1[8];
    int w = t >> 5, lane = t & 31;
    if (lane == 0) { r0[w] = s0; r1[w] = s1; }
    __syncthreads();
    if (t == 0) {
        float a0 = 0.f, a1 = 0.f;
#pragma unroll
        for (int k = 0; k < 8; k++) { a0 += r0[k]; a1 += r1[k]; }
        a0 += fc2b[0];
        a1 += fc2b[1];
        float mx = fmaxf(a0, a1);
        float lse = mx + logf(expf(a0 - mx) + expf(a1 - mx));
        out[2 * b + 0] = a0 - lse;
        out[2 * b + 1] = a1 - lse;
    }
}

extern "C" void kernel_launch(void* const* d_in, const int* in_sizes, int n_in,
                              void* d_out, int out_size) {
    const float* x  = (const float*)d_in[0];
    const int*   ei = (const int*)d_in[1];

    // batch_size may or may not be materialized as a size-1 input at index 2.
    // w0a has 128 elements -> detect.
    int base = (in_sizes[2] == 128) ? 2 : 3;

    const float* W[16];
    for (int k = 0; k < 16; k++) W[k] = (const float*)d_in[base + k];
    const float* fc1w = (const float*)d_in[base + 16];
    const float* fc1b = (const float*)d_in[base + 17];
    const float* fc2w = (const float*)d_in[base + 18];
    const float* fc2b = (const float*)d_in[base + 19];
    float* out = (float*)d_out;

    const int TB = 256;
    unsigned nodeBlocks = (N_TOTAL + TB - 1) / TB;
    unsigned s16Blocks  = ((unsigned)N_EDGES * 4 + TB - 1) / TB;  // 4 lanes/edge
    unsigned s8Blocks   = ((unsigned)N_EDGES * 2 + TB - 1) / TB;  // 2 lanes/edge
    unsigned zBlocks    = ((unsigned)N_TOTAL * 4 + TB - 1) / TB;

    // Layer 0
    zero_agg16<<<zBlocks, TB>>>();
    scatter16<<<s16Blocks, TB>>>(ei, x);
    mlp0_kernel<<<nodeBlocks, TB>>>(x, W[0], W[1], W[2], W[3]);

    // Layer 1
    scatter8<<<s8Blocks, TB>>>(ei);
    mlp_mid_kernel<<<nodeBlocks, TB>>>(W[4], W[5], W[6], W[7]);

    // Layer 2
    scatter8<<<s8Blocks, TB>>>(ei);
    mlp_mid_kernel<<<nodeBlocks, TB>>>(W[8], W[9], W[10], W[11]);

    // Layer 3 (+ fc1 fused)
    scatter8<<<s8Blocks, TB>>>(ei);
    mlp_last_kernel<<<nodeBlocks, TB>>>(W[12], W[13], W[14], W[15], fc1w, fc1b);

    // Readout
    readout_kernel<<<BATCH, TB>>>(fc2w, fc2b, out);
}

// round 5
// speedup vs baseline: 3.7273x; 1.5853x over previous
#include <cuda_runtime.h>

#define N_NODES 2000
#define BATCH 512
#define N_TOTAL (BATCH * N_NODES)      // 1,024,000
#define N_EDGES (16 * N_TOTAL)         // 16,384,000
#define SLOPE 0.01f
#define SENT N_TOTAL                   // sentinel node id -> permanently-zero row
#define CAP (N_EDGES + 3 * N_TOTAL + 16)  // padded CSR col capacity
#define NBLK 1000                      // scan blocks of 1024 elements (exactly covers N_TOTAL)

// -------- device scratch (no allocation; zero-initialized at load) --------
// NOTE: device globals are referenced ONLY from device code (host-side symbol
// decay to a kernel argument is invalid and was the round-4 bug).
__device__ __align__(16) int   g_deg[N_TOTAL];
__device__ __align__(16) int   g_cursor[N_TOTAL];
__device__ __align__(16) int   g_rs[N_TOTAL + 4];     // padded row starts, rs[N_TOTAL]=total
__device__ __align__(16) int   g_bsum[NBLK];
__device__ __align__(16) int   g_boff[NBLK];
__device__ __align__(16) int   g_col[CAP];
__device__ __align__(16) float g_ya[(size_t)(N_TOTAL + 1) * 8];  // +1: zero sentinel row (never written)
__device__ __align__(16) float g_yb[(size_t)(N_TOTAL + 1) * 8];
__device__ __align__(16) float g_z[N_TOTAL];

__device__ __forceinline__ float leaky(float v) { return v > 0.0f ? v : SLOPE * v; }

// ---------------- CSR build ----------------
__global__ void k_zero_deg() {
    int t = blockIdx.x * blockDim.x + threadIdx.x;       // int4 index
    if (t < N_TOTAL / 4) reinterpret_cast<int4*>(g_deg)[t] = make_int4(0, 0, 0, 0);
}

__global__ void k_hist(const int* __restrict__ ei) {
    unsigned e = blockIdx.x * blockDim.x + threadIdx.x;
    if (e < (unsigned)N_EDGES) {
        int dst = __ldg(ei + N_EDGES + e);
        atomicAdd(&g_deg[dst], 1);
    }
}

// scan1: per-block (1024 elems) exclusive scan of padded degrees
__global__ void k_scan1() {
    __shared__ int ssum[256];
    int blk = blockIdx.x, t = threadIdx.x;
    int idx = blk * 1024 + t * 4;
    int4 d = *reinterpret_cast<const int4*>(g_deg + idx);
    int p0 = (d.x + 3) & ~3, p1 = (d.y + 3) & ~3, p2 = (d.z + 3) & ~3, p3 = (d.w + 3) & ~3;
    int s01 = p0 + p1, s012 = s01 + p2, tot = s012 + p3;
    ssum[t] = tot;
    __syncthreads();
    for (int off = 1; off < 256; off <<= 1) {
        int v = (t >= off) ? ssum[t - off] : 0;
        __syncthreads();
        ssum[t] += v;
        __syncthreads();
    }
    int excl = ssum[t] - tot;
    int4 r = make_int4(excl, excl + p0, excl + s01, excl + s012);
    *reinterpret_cast<int4*>(g_rs + idx) = r;
    if (t == 255) g_bsum[blk] = ssum[255];
}

// scan2: single block scans the NBLK block sums
__global__ void k_scan2() {
    __shared__ int s[1024];
    int t = threadIdx.x;
    int v = (t < NBLK) ? g_bsum[t] : 0;
    s[t] = v;
    __syncthreads();
    for (int off = 1; off < 1024; off <<= 1) {
        int u = (t >= off) ? s[t - off] : 0;
        __syncthreads();
        s[t] += u;
        __syncthreads();
    }
    if (t < NBLK) g_boff[t] = s[t] - v;       // exclusive
    if (t == 1023) g_rs[N_TOTAL] = s[1023];   // grand total
}

// scan3: add block offsets; also init cursor = row start
__global__ void k_scan3() {
    int blk = blockIdx.x, t = threadIdx.x;
    int idx = blk * 1024 + t * 4;
    int off = g_boff[blk];
    int4 r = *reinterpret_cast<const int4*>(g_rs + idx);
    r.x += off; r.y += off; r.z += off; r.w += off;
    *reinterpret_cast<int4*>(g_rs + idx) = r;
    *reinterpret_cast<int4*>(g_cursor + idx) = r;
}

__global__ void k_sentinel() {
    unsigned t = blockIdx.x * blockDim.x + threadIdx.x;  // int4 index
    if (t < (unsigned)(CAP / 4))
        reinterpret_cast<int4*>(g_col)[t] = make_int4(SENT, SENT, SENT, SENT);
}

__global__ void k_fill(const int* __restrict__ ei) {
    unsigned e = blockIdx.x * blockDim.x + threadIdx.x;
    if (e < (unsigned)N_EDGES) {
        int src = __ldg(ei + e);
        int dst = __ldg(ei + N_EDGES + e);
        int pos = atomicAdd(&g_cursor[dst], 1);
        g_col[pos] = src;
    }
}

// ---------------- pretransform: g_ya = x @ w0a (no bias; folded by linearity) ----------------
__global__ void k_pre(const float* __restrict__ x, const float* __restrict__ w0a) {
    __shared__ float sw[128];
    int t = threadIdx.x;
    if (t < 128) sw[t] = w0a[t];
    __syncthreads();
    unsigned i = blockIdx.x * blockDim.x + t;
    if (i >= (unsigned)N_TOTAL) return;
    float in[16];
    const float4* ax = reinterpret_cast<const float4*>(x + (size_t)i * 16);
#pragma unroll
    for (int q = 0; q < 4; q++) {
        float4 a = ax[q];
        in[4 * q] = a.x; in[4 * q + 1] = a.y; in[4 * q + 2] = a.z; in[4 * q + 3] = a.w;
    }
    float y[8];
#pragma unroll
    for (int j = 0; j < 8; j++) y[j] = 0.f;
#pragma unroll
    for (int k = 0; k < 16; k++) {
        float v = in[k];
#pragma unroll
        for (int j = 0; j < 8; j++) y[j] = fmaf(v, sw[k * 8 + j], y[j]);
    }
    float4* py = reinterpret_cast<float4*>(g_ya + (size_t)i * 8);
    py[0] = make_float4(y[0], y[1], y[2], y[3]);
    py[1] = make_float4(y[4], y[5], y[6], y[7]);
}

// ---------------- fused gather + MLP (+ next-layer wa) ----------------
// flip=0: read g_ya, write g_yb ; flip=1: read g_yb, write g_ya
__global__ void k_gather_mlp(int flip,
                             const float* __restrict__ ba, const float* __restrict__ wb,
                             const float* __restrict__ bb, const float* __restrict__ wan) {
    const float* yin  = flip ? g_yb : g_ya;
    float*       yout = flip ? g_ya : g_yb;

    __shared__ float swb[64], swan[64], sba[8], sbb[8];
    int t = threadIdx.x;
    if (t < 64) { swb[t] = wb[t]; swan[t] = wan[t]; }
    if (t < 8)  { sba[t] = ba[t]; sbb[t] = bb[t]; }
    __syncthreads();

    unsigned g = blockIdx.x * blockDim.x + t;   // 2 lanes per node, exact multiple
    unsigned node = g >> 1;
    unsigned half = g & 1u;

    int rs = g_rs[node], re = g_rs[node + 1];
    // self term
    float4 acc = *reinterpret_cast<const float4*>(yin + (size_t)node * 8 + half * 4);
    for (int e = rs; e < re; e += 4) {
        int4 c = *reinterpret_cast<const int4*>(g_col + e);
        float4 v0 = __ldg(reinterpret_cast<const float4*>(yin + (size_t)c.x * 8 + half * 4));
        float4 v1 = __ldg(reinterpret_cast<const float4*>(yin + (size_t)c.y * 8 + half * 4));
        float4 v2 = __ldg(reinterpret_cast<const float4*>(yin + (size_t)c.z * 8 + half * 4));
        float4 v3 = __ldg(reinterpret_cast<const float4*>(yin + (size_t)c.w * 8 + half * 4));
        acc.x += v0.x + v1.x + v2.x + v3.x;
        acc.y += v0.y + v1.y + v2.y + v3.y;
        acc.z += v0.z + v1.z + v2.z + v3.z;
        acc.w += v0.w + v1.w + v2.w + v3.w;
    }
    // exchange halves with pair lane
    float o0 = __shfl_xor_sync(0xFFFFFFFFu, acc.x, 1);
    float o1 = __shfl_xor_sync(0xFFFFFFFFu, acc.y, 1);
    float o2 = __shfl_xor_sync(0xFFFFFFFFu, acc.z, 1);
    float o3 = __shfl_xor_sync(0xFFFFFFFFu, acc.w, 1);
    float in[8];
    if (half == 0) {
        in[0] = acc.x; in[1] = acc.y; in[2] = acc.z; in[3] = acc.w;
        in[4] = o0; in[5] = o1; in[6] = o2; in[7] = o3;
    } else {
        in[0] = o0; in[1] = o1; in[2] = o2; in[3] = o3;
        in[4] = acc.x; in[5] = acc.y; in[6] = acc.z; in[7] = acc.w;
    }

    float t1[8];
#pragma unroll
    for (int j = 0; j < 8; j++) t1[j] = leaky(in[j] + sba[j]);
    float t2[8];
#pragma unroll
    for (int j = 0; j < 8; j++) t2[j] = sbb[j];
#pragma unroll
    for (int k = 0; k < 8; k++) {
        float v = t1[k];
#pragma unroll
        for (int j = 0; j < 8; j++) t2[j] = fmaf(v, swb[k * 8 + j], t2[j]);
    }
#pragma unroll
    for (int j = 0; j < 8; j++) t2[j] = leaky(t2[j]);   // inter-layer act

    // next-layer pre-transform: this lane only needs its 4 output columns
    int jo = half * 4;
    float y0 = 0.f, y1 = 0.f, y2 = 0.f, y3 = 0.f;
#pragma unroll
    for (int k = 0; k < 8; k++) {
        float v = t2[k];
        y0 = fmaf(v, swan[k * 8 + jo + 0], y0);
        y1 = fmaf(v, swan[k * 8 + jo + 1], y1);
        y2 = fmaf(v, swan[k * 8 + jo + 2], y2);
        y3 = fmaf(v, swan[k * 8 + jo + 3], y3);
    }
    *reinterpret_cast<float4*>(yout + (size_t)node * 8 + half * 4) = make_float4(y0, y1, y2, y3);
}

// Last layer (reads g_yb): z = fc1( leaky( leaky(agg + b3a) @ w3b + b3b ) )
__global__ void k_gather_last(const float* __restrict__ ba, const float* __restrict__ wb,
                              const float* __restrict__ bb,
                              const float* __restrict__ fc1w, const float* __restrict__ fc1b) {
    const float* yin = g_yb;

    __shared__ float swb[64], sba[8], sbb[8], sf1[8], sf1b;
    int t = threadIdx.x;
    if (t < 64) swb[t] = wb[t];
    if (t < 8)  { sba[t] = ba[t]; sbb[t] = bb[t]; sf1[t] = fc1w[t]; }
    if (t == 0) sf1b = fc1b[0];
    __syncthreads();

    unsigned g = blockIdx.x * blockDim.x + t;
    unsigned node = g >> 1;
    unsigned half = g & 1u;

    int rs = g_rs[node], re = g_rs[node + 1];
    float4 acc = *reinterpret_cast<const float4*>(yin + (size_t)node * 8 + half * 4);
    for (int e = rs; e < re; e += 4) {
        int4 c = *reinterpret_cast<const int4*>(g_col + e);
        float4 v0 = __ldg(reinterpret_cast<const float4*>(yin + (size_t)c.x * 8 + half * 4));
        float4 v1 = __ldg(reinterpret_cast<const float4*>(yin + (size_t)c.y * 8 + half * 4));
        float4 v2 = __ldg(reinterpret_cast<const float4*>(yin + (size_t)c.z * 8 + half * 4));
        float4 v3 = __ldg(reinterpret_cast<const float4*>(yin + (size_t)c.w * 8 + half * 4));
        acc.x += v0.x + v1.x + v2.x + v3.x;
        acc.y += v0.y + v1.y + v2.y + v3.y;
        acc.z += v0.z + v1.z + v2.z + v3.z;
        acc.w += v0.w + v1.w + v2.w + v3.w;
    }
    float o0 = __shfl_xor_sync(0xFFFFFFFFu, acc.x, 1);
    float o1 = __shfl_xor_sync(0xFFFFFFFFu, acc.y, 1);
    float o2 = __shfl_xor_sync(0xFFFFFFFFu, acc.z, 1);
    float o3 = __shfl_xor_sync(0xFFFFFFFFu, acc.w, 1);
    float in[8];
    if (half == 0) {
        in[0] = acc.x; in[1] = acc.y; in[2] = acc.z; in[3] = acc.w;
        in[4] = o0; in[5] = o1; in[6] = o2; in[7] = o3;
    } else {
        in[0] = o0; in[1] = o1; in[2] = o2; in[3] = o3;
        in[4] = acc.x; in[5] = acc.y; in[6] = acc.z; in[7] = acc.w;
    }

    float t1[8];
#pragma unroll
    for (int j = 0; j < 8; j++) t1[j] = leaky(in[j] + sba[j]);
    float t2[8];
#pragma unroll
    for (int j = 0; j < 8; j++) t2[j] = sbb[j];
#pragma unroll
    for (int k = 0; k < 8; k++) {
        float v = t1[k];
#pragma unroll
        for (int j = 0; j < 8; j++) t2[j] = fmaf(v, swb[k * 8 + j], t2[j]);
    }
    // no inter-layer act; readout applies leaky before fc1
    float z = sf1b;
#pragma unroll
    for (int j = 0; j < 8; j++) z = fmaf(leaky(t2[j]), sf1[j], z);
    if (half == 0) g_z[node] = z;
}

// ---------------- readout: per-graph fc2 + log_softmax ----------------
__global__ void readout_kernel(const float* __restrict__ fc2w, const float* __restrict__ fc2b,
                               float* __restrict__ out) {
    int b = blockIdx.x;
    int t = threadIdx.x;
    float s0 = 0.f, s1 = 0.f;
    const float* zb = g_z + (size_t)b * N_NODES;
    for (int n = t; n < N_NODES; n += blockDim.x) {
        float zv = leaky(zb[n]);
        float2 w = __ldg(reinterpret_cast<const float2*>(fc2w) + n);
        s0 = fmaf(zv, w.x, s0);
        s1 = fmaf(zv, w.y, s1);
    }
#pragma unroll
    for (int o = 16; o > 0; o >>= 1) {
        s0 += __shfl_down_sync(0xFFFFFFFFu, s0, o);
        s1 += __shfl_down_sync(0xFFFFFFFFu, s1, o);
    }
    __shared__ float r0[8], r1[8];
    int w = t >> 5, lane = t & 31;
    if (lane == 0) { r0[w] = s0; r1[w] = s1; }
    __syncthreads();
    if (t == 0) {
        float a0 = 0.f, a1 = 0.f;
#pragma unroll
        for (int k = 0; k < 8; k++) { a0 += r0[k]; a1 += r1[k]; }
        a0 += fc2b[0];
        a1 += fc2b[1];
        float mx = fmaxf(a0, a1);
        float lse = mx + logf(expf(a0 - mx) + expf(a1 - mx));
        out[2 * b + 0] = a0 - lse;
        out[2 * b + 1] = a1 - lse;
    }
}

extern "C" void kernel_launch(void* const* d_in, const int* in_sizes, int n_in,
                              void* d_out, int out_size) {
    const float* x  = (const float*)d_in[0];
    const int*   ei = (const int*)d_in[1];

    int base = (in_sizes[2] == 128) ? 2 : 3;   // batch_size may not be materialized

    const float* W[16];
    for (int k = 0; k < 16; k++) W[k] = (const float*)d_in[base + k];
    const float* fc1w = (const float*)d_in[base + 16];
    const float* fc1b = (const float*)d_in[base + 17];
    const float* fc2w = (const float*)d_in[base + 18];
    const float* fc2b = (const float*)d_in[base + 19];
    float* out = (float*)d_out;

    const int TB = 256;
    unsigned edgeBlocks = (N_EDGES + TB - 1) / TB;
    unsigned nodeBlocks = (N_TOTAL + TB - 1) / TB;
    unsigned pairBlocks = (N_TOTAL * 2) / TB;          // exact
    unsigned sentBlocks = ((CAP / 4) + TB - 1) / TB;

    // CSR build (per launch; reused by all 4 layers)
    k_zero_deg<<<(N_TOTAL / 4 + TB - 1) / TB, TB>>>();
    k_hist<<<edgeBlocks, TB>>>(ei);
    k_scan1<<<NBLK, 256>>>();
    k_scan2<<<1, 1024>>>();
    k_scan3<<<NBLK, 256>>>();
    k_sentinel<<<sentBlocks, TB>>>();
    k_fill<<<edgeBlocks, TB>>>(ei);

    // Layer pipeline (all aggregation in pre-transformed 8-wide space)
    k_pre<<<nodeBlocks, TB>>>(x, W[0]);                                   // g_ya = x @ w0a
    k_gather_mlp<<<pairBlocks, TB>>>(0, W[1], W[2], W[3], W[4]);          // L0: ya -> yb (w1a folded)
    k_gather_mlp<<<pairBlocks, TB>>>(1, W[5], W[6], W[7], W[8]);          // L1: yb -> ya
    k_gather_mlp<<<pairBlocks, TB>>>(0, W[9], W[10], W[11], W[12]);       // L2: ya -> yb
    k_gather_last<<<pairBlocks, TB>>>(W[13], W[14], W[15], fc1w, fc1b);   // L3 + fc1 -> g_z

    readout_kernel<<<BATCH, TB>>>(fc2w, fc2b, out);
}